// round 17
// baseline (speedup 1.0000x reference)
#include <cuda_runtime.h>

// CorrTorch 3D correlation, max_displacement=1.
// in1, in2: [1, 64, 64, 128, 128] fp32; out: [1, 27, 64, 128, 128] fp32.
//
// R16 -> R17: prefetch abandoned (L2=99% both with and without .nc; no L1
// conversion). Back to R10 skeleton, attacking the dominant issue class:
// 36 scalar FMAs -> 18 FFMA2 on NATURALLY ALIGNED pairs only. Unlike R12
// (which needed in-loop unpacks + scalar halo FMAs -> MOV bloat), every tap
// group maps to aligned (x,y)/(z,w) pairs from the float4 loads:
//   dx1: A01*r01, A23*r23        dx0: A12*r01 -> (o1,o2), A3n*r23 -> (o3,X)
//   dx2: Ap0*r01 -> (Y,o0),      A12*r23 -> (o1,o2)
// Only A12/A3n/Ap0 are real packs (~6 MOV/ch); accumulators stay packed, all
// unpacking happens once in the epilogue. Units/warp-channel ~49 -> ~34.
// Everything else bit-identical to R10: pinned .nc LDG.128s, 2-stage
// pipeline, (64,3)x192 blocks, launch_bounds(192,4).

namespace {
constexpr int C  = 64;
constexpr int DD = 64;
constexpr int HH = 128;
constexpr int WW = 128;
constexpr int HW = HH * WW;        // 16384
constexpr int CS = DD * HW;        // 1048576
constexpr int TPX = 64;            // 2 warps in x, each = one full W row
constexpr int NBLK = DD * HH * (WW / 4) / TPX;   // 4096
}

using u64 = unsigned long long;

__device__ __forceinline__ void fma2(u64& d, u64 a, u64 b) {
    asm("fma.rn.f32x2 %0, %1, %2, %0;" : "+l"(d) : "l"(a), "l"(b));
}
__device__ __forceinline__ u64 pack2(float lo, float hi) {
    u64 r; asm("mov.b64 %0, {%1, %2};" : "=l"(r) : "f"(lo), "f"(hi)); return r;
}
__device__ __forceinline__ float2 unpack2(u64 v) {
    float2 r; asm("mov.b64 {%0, %1}, %2;" : "=f"(r.x), "=f"(r.y) : "l"(v)); return r;
}

__device__ __forceinline__ float4 ldg128(const float* p) {
    float4 v;
    asm volatile("ld.global.nc.v4.f32 {%0,%1,%2,%3}, [%4];"
                 : "=f"(v.x), "=f"(v.y), "=f"(v.z), "=f"(v.w)
                 : "l"(p));
    return v;
}

__device__ __forceinline__ float4 ldg128_pred(const float* p, int pred) {
    float4 v;
    asm volatile("{\n\t"
        ".reg .pred q;\n\t"
        "setp.ne.s32 q, %5, 0;\n\t"
        "mov.f32 %0, 0f00000000;\n\t"
        "mov.f32 %1, 0f00000000;\n\t"
        "mov.f32 %2, 0f00000000;\n\t"
        "mov.f32 %3, 0f00000000;\n\t"
        "@q ld.global.nc.v4.f32 {%0,%1,%2,%3}, [%4];\n\t"
        "}"
        : "=f"(v.x), "=f"(v.y), "=f"(v.z), "=f"(v.w)
        : "l"(p), "r"(pred));
    return v;
}

struct Acc {
    u64 d1a[3];   // dx=1: (out0,out1)
    u64 d1b[3];   // dx=1: (out2,out3)
    u64 d0m[3];   // dx=0: (out1,out2)
    u64 d0h[3];   // dx=0: (out3, X-halo)   X -> right neighbor's out0
    u64 d2h[3];   // dx=2: (Y-halo, out0)   Y -> left neighbor's out3
    u64 d2m[3];   // dx=2: (out1,out2)
};

__device__ __forceinline__ void ld_stage(const float* __restrict__ q1,
                                         const float* __restrict__ q2,
                                         const int rv[3],
                                         float4& a, float4 rm[3])
{
    a = ldg128(q1);
#pragma unroll
    for (int dy = 0; dy < 3; dy++) {
        rm[dy] = ldg128_pred(q2 + dy * WW, rv[dy]);
    }
}

__device__ __forceinline__ void do_compute(const float4& a, const float4 rm[3],
                                           Acc& A)
{
    float an0 = __shfl_down_sync(0xffffffffu, a.x, 1);  // right lane's a0
    float ap3 = __shfl_up_sync  (0xffffffffu, a.w, 1);  // left lane's a3
    // aligned aliases (free: float4 lands in aligned reg pairs)
    u64 A01 = pack2(a.x, a.y);
    u64 A23 = pack2(a.z, a.w);
    // real packs (~2 MOV each)
    u64 A12 = pack2(a.y, a.z);
    u64 A3n = pack2(a.w, an0);
    u64 Ap0 = pack2(ap3, a.x);
#pragma unroll
    for (int dy = 0; dy < 3; dy++) {
        u64 r01 = pack2(rm[dy].x, rm[dy].y);   // aligned alias
        u64 r23 = pack2(rm[dy].z, rm[dy].w);   // aligned alias
        fma2(A.d1a[dy], A01, r01);  // dx=1: o0+=a0r0, o1+=a1r1
        fma2(A.d1b[dy], A23, r23);  // dx=1: o2+=a2r2, o3+=a3r3
        fma2(A.d0m[dy], A12, r01);  // dx=0: o1+=a1r0, o2+=a2r1
        fma2(A.d0h[dy], A3n, r23);  // dx=0: o3+=a3r2, X+=an0*r3
        fma2(A.d2h[dy], Ap0, r01);  // dx=2: Y+=ap3*r0, o0+=a0r1
        fma2(A.d2m[dy], A12, r23);  // dx=2: o1+=a1r2, o2+=a2r3
    }
}

__global__ void __launch_bounds__(TPX * 3, 4) corr3d_kernel(
    const float* __restrict__ in1,
    const float* __restrict__ in2,
    float* __restrict__ out)
{
    const int s  = blockIdx.x * TPX + threadIdx.x;  // strip id
    const int dz = threadIdx.y;                     // 0..2
    const int lane = threadIdx.x & 31;
    const int w0 = (s & 31) << 2;                   // 0,4,...,124
    const int h  = (s >> 5) & 127;
    const int d  = s >> 12;

    const int zp = d + dz - 1;                      // in2 source plane
    const int pz = (zp >= 0) && (zp < DD);
    const int rv[3] = { pz && (h > 0), pz, pz && (h < HH - 1) };
    const bool pw0 = (lane > 0);
    const bool pw5 = (lane < 31);

    const float* q1 = in1 + d * HW + h * WW + w0;
    const float* q2 = in2 + zp * HW + (h - 1) * WW + w0;

    Acc A;
#pragma unroll
    for (int dy = 0; dy < 3; dy++) {
        A.d1a[dy] = 0; A.d1b[dy] = 0; A.d0m[dy] = 0;
        A.d0h[dy] = 0; A.d2h[dy] = 0; A.d2m[dy] = 0;
    }

    float4 aA, aB;
    float4 rmA[3], rmB[3];

    ld_stage(q1, q2, rv, aA, rmA);                  // c = 0

#pragma unroll 2
    for (int c = 0; c < C - 2; c += 2) {
        q1 += CS; q2 += CS;
        ld_stage(q1, q2, rv, aB, rmB);              // c+1 in flight
        do_compute(aA, rmA, A);                     // consume c
        q1 += CS; q2 += CS;
        ld_stage(q1, q2, rv, aA, rmA);              // c+2 in flight
        do_compute(aB, rmB, A);                     // consume c+1
    }
    q1 += CS; q2 += CS;
    ld_stage(q1, q2, rv, aB, rmB);                  // c = C-1
    do_compute(aA, rmA, A);
    do_compute(aB, rmB, A);

    float* op = out + (long)(dz * 9) * CS + d * HW + h * WW + w0;
    const float inv = 1.0f / 64.0f;
#pragma unroll
    for (int dy = 0; dy < 3; dy++) {
        // dx = 0: (o1,o2) in d0m, (o3, X) in d0h; out0 from left neighbor's X
        float2 q12 = unpack2(A.d0m[dy]);
        float2 q3X = unpack2(A.d0h[dy]);
        float xin = __shfl_up_sync(0xffffffffu, q3X.y, 1);
        float4 v0 = make_float4(pw0 ? xin * inv : 0.f,
                                q12.x * inv, q12.y * inv, q3X.x * inv);
        *reinterpret_cast<float4*>(op + (long)(dy * 3 + 0) * CS) = v0;
        // dx = 1
        float2 p01 = unpack2(A.d1a[dy]);
        float2 p23 = unpack2(A.d1b[dy]);
        float4 v1 = make_float4(p01.x * inv, p01.y * inv,
                                p23.x * inv, p23.y * inv);
        *reinterpret_cast<float4*>(op + (long)(dy * 3 + 1) * CS) = v1;
        // dx = 2: (Y, o0) in d2h, (o1,o2) in d2m; out3 from right neighbor's Y
        float2 sY0 = unpack2(A.d2h[dy]);
        float2 s12 = unpack2(A.d2m[dy]);
        float yin = __shfl_down_sync(0xffffffffu, sY0.x, 1);
        float4 v2 = make_float4(sY0.y * inv, s12.x * inv, s12.y * inv,
                                pw5 ? yin * inv : 0.f);
        *reinterpret_cast<float4*>(op + (long)(dy * 3 + 2) * CS) = v2;
    }
}

extern "C" void kernel_launch(void* const* d_in, const int* in_sizes, int n_in,
                              void* d_out, int out_size)
{
    const float* in1 = (const float*)d_in[0];
    const float* in2 = (const float*)d_in[1];
    float* out = (float*)d_out;
    (void)in_sizes; (void)n_in; (void)out_size;

    dim3 blk(TPX, 3);
    corr3d_kernel<<<NBLK, blk>>>(in1, in2, out);
}